// round 6
// baseline (speedup 1.0000x reference)
#include <cuda_runtime.h>
#include <cuda_bf16.h>

#define NBIN 25
#define WARPS_PER_BLOCK 8
#define MAX_B 64
#define MAX_SLOTS 1024

// Per-block partial sums, written with plain stores every launch (no zeroing
// needed). Layout: slot = s*B + b so the last-block reduction reads are
// coalesced (stride B*NBIN across thread index).
__device__ float g_pnum[MAX_SLOTS * NBIN];
__device__ float g_pden[MAX_SLOTS * NBIN];
__device__ float g_plab[MAX_SLOTS];
__device__ unsigned int g_ticket = 0;   // reset to 0 by the last block each run

// ---------------------------------------------------------------------------
// Single fused kernel: streaming cosine-sim + binning, then the block that
// finishes last reduces all partials (L2-hot) and writes the scalar output.
// 8 lanes per row, 4 rows per warp. grid = B*S blocks = one exact wave at
// 5 blocks/SM (launch_bounds caps regs at 51 to lift occupancy 30->40 warps).
// Hot loop: plain float4 loads — cache hints regressed DRAM 6.3 -> 4.2 TB/s.
// ---------------------------------------------------------------------------
__global__ __launch_bounds__(WARPS_PER_BLOCK * 32, 5)
void qap_main(const float4* __restrict__ qX4,
              const float4* __restrict__ dXs4,
              const int*    __restrict__ labels,
              float* __restrict__ out,
              int B, int N, int S) {
    const int b    = blockIdx.x / S;     // batch
    const int s    = blockIdx.x - b * S; // slice within batch
    const int lane = threadIdx.x & 31;
    const int warp = threadIdx.x >> 5;
    const int sub  = lane & 7;           // slice within row (8 lanes/row)
    const int grp  = lane >> 3;          // row within warp-iteration (4 rows)
    const int gw     = s * WARPS_PER_BLOCK + warp;
    const int nWarps = S * WARPS_PER_BLOCK;

    // Per-lane slices of qX[b]: float4 indices sub + 8j.
    float4 qv[4];
    #pragma unroll
    for (int j = 0; j < 4; j++) qv[j] = qX4[(size_t)b * 32 + sub + 8 * j];

    // ||q||, reduced over the 8-lane group.
    float qs = 0.0f;
    #pragma unroll
    for (int j = 0; j < 4; j++)
        qs += qv[j].x * qv[j].x + qv[j].y * qv[j].y + qv[j].z * qv[j].z + qv[j].w * qv[j].w;
    #pragma unroll
    for (int off = 4; off; off >>= 1) qs += __shfl_xor_sync(0xFFFFFFFFu, qs, off);
    const float invqn = 1.0f / fmaxf(sqrtf(qs), 1e-8f);

    const float4* __restrict__ drow = dXs4   + (size_t)b * N * 32;
    const int*    __restrict__ lrow = labels + (size_t)b * N;

    // Lane k accumulates bin k. DELTA = 2/(NBIN-1) = 1/12.
    const float ck   = 1.0f - (float)lane * (2.0f / (float)(NBIN - 1));
    const float invD = (float)(NBIN - 1) * 0.5f;   // 12

    float accNum = 0.0f, accDen = 0.0f, accLab = 0.0f;

    const int nTiles = (N + 31) >> 5;      // 32-row tiles
    for (int t = gw; t < nTiles; t += nWarps) {
        const int tile = t << 5;
        const int cnt  = min(32, N - tile);
        const int lab32 = (lane < cnt) ? lrow[tile + lane] : 0;
        accLab += (float)lab32;

        #pragma unroll 2
        for (int i = 0; i < 8; i++) {      // 4 rows per iteration
            const int r0 = tile + (i << 2);
            if (r0 >= N) break;
            const int myrow   = r0 + grp;
            const int loadrow = (myrow < N) ? myrow : (N - 1);
            const float4* __restrict__ p = drow + (size_t)loadrow * 32 + sub;

            float d = 0.0f, sq = 0.0f;
            #pragma unroll
            for (int j = 0; j < 4; j++) {
                const float4 x = p[8 * j];
                d  += qv[j].x * x.x + qv[j].y * x.y + qv[j].z * x.z + qv[j].w * x.w;
                sq += x.x * x.x + x.y * x.y + x.z * x.z + x.w * x.w;
            }
            #pragma unroll
            for (int off = 4; off; off >>= 1) {
                d  += __shfl_xor_sync(0xFFFFFFFFu, d,  off);
                sq += __shfl_xor_sync(0xFFFFFFFFu, sq, off);
            }
            // sim = d / (qn * max(sqrt(sq),1e-8)); sq >= 1e-16 -> rsqrt form.
            const float sim = d * invqn * rsqrtf(fmaxf(sq, 1e-16f));

            #pragma unroll
            for (int r = 0; r < 4; r++) {
                if (r0 + r >= N) break;   // uniform branch
                const float simr = __shfl_sync(0xFFFFFFFFu, sim, r << 3);
                const float labr = (float)__shfl_sync(0xFFFFFFFFu, lab32, (i << 2) + r);
                const float sa = fmaxf(0.0f, fmaf(-invD, fabsf(simr - ck), 1.0f));
                accDen += sa;
                accNum += sa * labr;
            }
        }
    }

    // Warp-reduce the per-lane label partials.
    #pragma unroll
    for (int off = 16; off; off >>= 1)
        accLab += __shfl_xor_sync(0xFFFFFFFFu, accLab, off);

    // Block-level combine in smem, then one plain store per bin.
    __shared__ float s_num[NBIN], s_den[NBIN], s_lab;
    if (threadIdx.x < NBIN) { s_num[threadIdx.x] = 0.0f; s_den[threadIdx.x] = 0.0f; }
    if (threadIdx.x == 0) s_lab = 0.0f;
    __syncthreads();
    if (lane < NBIN) {
        atomicAdd(&s_den[lane], accDen);
        atomicAdd(&s_num[lane], accNum);
    }
    if (lane == 0) atomicAdd(&s_lab, accLab);
    __syncthreads();

    const int slot = s * B + b;
    if (threadIdx.x < NBIN) {
        g_pnum[slot * NBIN + threadIdx.x] = s_num[threadIdx.x];
        g_pden[slot * NBIN + threadIdx.x] = s_den[threadIdx.x];
    }
    if (threadIdx.x == 0) g_plab[slot] = s_lab;

    // ---- last-block reduction (threadfence-reduction pattern) ----
    __shared__ unsigned int s_last;
    __threadfence();
    if (threadIdx.x == 0) {
        unsigned int old = atomicAdd(&g_ticket, 1u);
        s_last = (old == (unsigned int)(gridDim.x - 1)) ? 1u : 0u;
    }
    __syncthreads();
    if (!s_last) return;

    // This block sees all partials (fence + atomic chain). They are L2-hot.
    // Keep this loop pragma-free so it doesn't steal registers from the hot loop.
    __shared__ float r_num[MAX_B * NBIN], r_den[MAX_B * NBIN], r_lab[MAX_B];
    const int total = B * NBIN;
    for (int i = threadIdx.x; i < total; i += blockDim.x) {
        float a = 0.0f, c = 0.0f;
        for (int sidx = 0; sidx < S; sidx++) {     // coalesced: stride = total
            a += g_pnum[sidx * total + i];
            c += g_pden[sidx * total + i];
        }
        r_num[i] = a; r_den[i] = c;
    }
    if (threadIdx.x < B) {
        float l = 0.0f;
        for (int sidx = 0; sidx < S; sidx++) l += g_plab[sidx * B + threadIdx.x];
        r_lab[threadIdx.x] = l;
    }
    __syncthreads();

    if (threadIdx.x < 32) {
        float ap = 0.0f;
        if (threadIdx.x < B) {
            float pd = 0.0f;           // cumsum num_per_bin  ("pDen")
            float pn = 1e-16f;         // EPS_P + cumsum den_per_bin ("pNum")
            const float invLab = 1.0f / r_lab[threadIdx.x];
            for (int k = 0; k < NBIN; k++) {
                const float nm = r_num[threadIdx.x * NBIN + k];
                const float dn = r_den[threadIdx.x * NBIN + k];
                pd += nm;
                pn += dn;
                ap += (pd / pn) * (nm * invLab);
            }
        }
        #pragma unroll
        for (int off = 16; off; off >>= 1) ap += __shfl_xor_sync(0xFFFFFFFFu, ap, off);
        if (threadIdx.x == 0) {
            out[0] = ap / (float)B;
            g_ticket = 0;              // reset for the next graph replay
        }
    }
}

// ---------------------------------------------------------------------------
extern "C" void kernel_launch(void* const* d_in, const int* in_sizes, int n_in,
                              void* d_out, int out_size) {
    const float4* qX4    = (const float4*)d_in[0];
    const float4* dXs4   = (const float4*)d_in[1];
    const int*    labels = (const int*)d_in[2];
    float* out = (float*)d_out;

    const int M = 128;
    const int B = in_sizes[0] / M;               // 16
    const int N = in_sizes[1] / in_sizes[0];     // 50000

    // One exact wave at 5 blocks/SM: 148 * 5 = 740 slots -> use 736 (B*46).
    int S = (148 * 5) / B;                       // 46 for B=16
    if (S < 1) S = 1;
    if ((size_t)B * S > MAX_SLOTS) S = MAX_SLOTS / B;

    qap_main<<<B * S, WARPS_PER_BLOCK * 32>>>(qX4, dXs4, labels, out, B, N, S);
}

// round 10
// speedup vs baseline: 1.2491x; 1.2491x over previous
#include <cuda_runtime.h>
#include <cuda_bf16.h>

#define NBIN 25
#define WARPS_PER_BLOCK 8
#define MAX_B 64
#define MAX_SLOTS 1024

// Per-block partial sums, written with plain stores every launch (no zeroing
// needed). Layout: slot = s*B + b so the last-block reduction reads are
// coalesced (stride B*NBIN across thread index).
__device__ float g_pnum[MAX_SLOTS * NBIN];
__device__ float g_pden[MAX_SLOTS * NBIN];
__device__ float g_plab[MAX_SLOTS];
__device__ unsigned int g_ticket = 0;   // reset to 0 by the last block each run

// ---------------------------------------------------------------------------
// Single fused kernel. 8 lanes per row, 4 rows per warp-group-iteration.
// 32-row tile fully unrolled with a 1-group-deep load pipeline: group i+1's
// four LDG.128 are issued before group i's shuffle chain, keeping ~8 loads
// in flight per warp (the R6 experiment showed per-warp MLP, not occupancy,
// is the binding constraint). 64 regs @ 4 blocks/SM.
// Plain float4 loads — cache hints regressed DRAM 6.3 -> 4.2 TB/s (R4).
// ---------------------------------------------------------------------------
__global__ __launch_bounds__(WARPS_PER_BLOCK * 32, 4)
void qap_main(const float4* __restrict__ qX4,
              const float4* __restrict__ dXs4,
              const int*    __restrict__ labels,
              float* __restrict__ out,
              int B, int N, int S) {
    const int b    = blockIdx.x / S;     // batch
    const int s    = blockIdx.x - b * S; // slice within batch
    const int lane = threadIdx.x & 31;
    const int warp = threadIdx.x >> 5;
    const int sub  = lane & 7;           // slice within row (8 lanes/row)
    const int grp  = lane >> 3;          // row within 4-row group
    const int gw     = s * WARPS_PER_BLOCK + warp;
    const int nWarps = S * WARPS_PER_BLOCK;

    // Per-lane slices of qX[b]: float4 indices sub + 8j.
    float4 qv[4];
    #pragma unroll
    for (int j = 0; j < 4; j++) qv[j] = qX4[(size_t)b * 32 + sub + 8 * j];

    // ||q||, reduced over the 8-lane group.
    float qs = 0.0f;
    #pragma unroll
    for (int j = 0; j < 4; j++)
        qs += qv[j].x * qv[j].x + qv[j].y * qv[j].y + qv[j].z * qv[j].z + qv[j].w * qv[j].w;
    #pragma unroll
    for (int off = 4; off; off >>= 1) qs += __shfl_xor_sync(0xFFFFFFFFu, qs, off);
    const float invqn = 1.0f / fmaxf(sqrtf(qs), 1e-8f);

    const float4* __restrict__ drow = dXs4   + (size_t)b * N * 32;
    const int*    __restrict__ lrow = labels + (size_t)b * N;

    // Lane k accumulates bin k. DELTA = 2/(NBIN-1) = 1/12.
    const float ck   = 1.0f - (float)lane * (2.0f / (float)(NBIN - 1));
    const float invD = (float)(NBIN - 1) * 0.5f;   // 12

    float accNum = 0.0f, accDen = 0.0f, accLab = 0.0f;

    const int nFull = N >> 5;              // full 32-row tiles
    for (int t = gw; t < nFull; t += nWarps) {
        const int tile = t << 5;
        const float labf = (float)lrow[tile + lane];
        accLab += labf;

        // Base pointer for this lane's row in group 0; group i is +i*128
        // float4s (2048 B) -> all 32 loads use immediate offsets.
        const float4* __restrict__ base = drow + (size_t)tile * 32 + (grp << 5) + sub;

        float4 x[4], xn[4];
        #pragma unroll
        for (int j = 0; j < 4; j++) x[j] = base[8 * j];

        #pragma unroll
        for (int i = 0; i < 8; i++) {      // 4 rows per group, pipelined
            if (i < 7) {
                #pragma unroll
                for (int j = 0; j < 4; j++) xn[j] = base[(i + 1) * 128 + 8 * j];
            }
            float d = 0.0f, sq = 0.0f;
            #pragma unroll
            for (int j = 0; j < 4; j++) {
                d  += qv[j].x * x[j].x + qv[j].y * x[j].y + qv[j].z * x[j].z + qv[j].w * x[j].w;
                sq += x[j].x * x[j].x + x[j].y * x[j].y + x[j].z * x[j].z + x[j].w * x[j].w;
            }
            #pragma unroll
            for (int off = 4; off; off >>= 1) {
                d  += __shfl_xor_sync(0xFFFFFFFFu, d,  off);
                sq += __shfl_xor_sync(0xFFFFFFFFu, sq, off);
            }
            // sim = d / (qn * max(sqrt(sq),1e-8)); sq clamp -> rsqrt form.
            const float sim = d * invqn * rsqrtf(fmaxf(sq, 1e-16f));

            #pragma unroll
            for (int r = 0; r < 4; r++) {
                const float simr = __shfl_sync(0xFFFFFFFFu, sim,  r << 3);
                const float labr = __shfl_sync(0xFFFFFFFFu, labf, (i << 2) + r);
                const float sa = fmaxf(0.0f, fmaf(-invD, fabsf(simr - ck), 1.0f));
                accDen += sa;
                accNum += sa * labr;
            }
            #pragma unroll
            for (int j = 0; j < 4; j++) x[j] = xn[j];   // renamed, not moved
        }
    }

    // ---- tail rows (N % 32), one warp only, guarded path ----
    const int tailStart = nFull << 5;
    if (tailStart < N && gw == (nFull % nWarps)) {
        const int cnt = N - tailStart;     // 1..31
        const float labf = (lane < cnt) ? (float)lrow[tailStart + lane] : 0.0f;
        accLab += labf;
        for (int i = 0; i < 8; i++) {
            const int r0 = tailStart + (i << 2);
            if (r0 >= N) break;
            const int myrow   = r0 + grp;
            const int loadrow = (myrow < N) ? myrow : (N - 1);
            const float4* __restrict__ p = drow + (size_t)loadrow * 32 + sub;
            float d = 0.0f, sq = 0.0f;
            #pragma unroll
            for (int j = 0; j < 4; j++) {
                const float4 x = p[8 * j];
                d  += qv[j].x * x.x + qv[j].y * x.y + qv[j].z * x.z + qv[j].w * x.w;
                sq += x.x * x.x + x.y * x.y + x.z * x.z + x.w * x.w;
            }
            #pragma unroll
            for (int off = 4; off; off >>= 1) {
                d  += __shfl_xor_sync(0xFFFFFFFFu, d,  off);
                sq += __shfl_xor_sync(0xFFFFFFFFu, sq, off);
            }
            const float sim = d * invqn * rsqrtf(fmaxf(sq, 1e-16f));
            #pragma unroll
            for (int r = 0; r < 4; r++) {
                if (r0 + r >= N) break;    // uniform branch
                const float simr = __shfl_sync(0xFFFFFFFFu, sim,  r << 3);
                const float labr = __shfl_sync(0xFFFFFFFFu, labf, (i << 2) + r);
                const float sa = fmaxf(0.0f, fmaf(-invD, fabsf(simr - ck), 1.0f));
                accDen += sa;
                accNum += sa * labr;
            }
        }
    }

    // Warp-reduce the per-lane label partials.
    #pragma unroll
    for (int off = 16; off; off >>= 1)
        accLab += __shfl_xor_sync(0xFFFFFFFFu, accLab, off);

    // Block-level combine in smem, then one plain store per bin.
    __shared__ float s_num[NBIN], s_den[NBIN], s_lab;
    if (threadIdx.x < NBIN) { s_num[threadIdx.x] = 0.0f; s_den[threadIdx.x] = 0.0f; }
    if (threadIdx.x == 0) s_lab = 0.0f;
    __syncthreads();
    if (lane < NBIN) {
        atomicAdd(&s_den[lane], accDen);
        atomicAdd(&s_num[lane], accNum);
    }
    if (lane == 0) atomicAdd(&s_lab, accLab);
    __syncthreads();

    const int slot = s * B + b;
    if (threadIdx.x < NBIN) {
        g_pnum[slot * NBIN + threadIdx.x] = s_num[threadIdx.x];
        g_pden[slot * NBIN + threadIdx.x] = s_den[threadIdx.x];
    }
    if (threadIdx.x == 0) g_plab[slot] = s_lab;

    // ---- last-block reduction (threadfence-reduction pattern) ----
    __shared__ unsigned int s_last;
    __threadfence();
    if (threadIdx.x == 0) {
        unsigned int old = atomicAdd(&g_ticket, 1u);
        s_last = (old == (unsigned int)(gridDim.x - 1)) ? 1u : 0u;
    }
    __syncthreads();
    if (!s_last) return;

    // Partials are L2-hot here. Keep pragma-free (register hygiene).
    __shared__ float r_num[MAX_B * NBIN], r_den[MAX_B * NBIN], r_lab[MAX_B];
    const int total = B * NBIN;
    for (int i = threadIdx.x; i < total; i += blockDim.x) {
        float a = 0.0f, c = 0.0f;
        for (int sidx = 0; sidx < S; sidx++) {     // coalesced: stride = total
            a += g_pnum[sidx * total + i];
            c += g_pden[sidx * total + i];
        }
        r_num[i] = a; r_den[i] = c;
    }
    if (threadIdx.x < B) {
        float l = 0.0f;
        for (int sidx = 0; sidx < S; sidx++) l += g_plab[sidx * B + threadIdx.x];
        r_lab[threadIdx.x] = l;
    }
    __syncthreads();

    if (threadIdx.x < 32) {
        float ap = 0.0f;
        if (threadIdx.x < B) {
            float pd = 0.0f;           // cumsum num_per_bin  ("pDen")
            float pn = 1e-16f;         // EPS_P + cumsum den_per_bin ("pNum")
            const float invLab = 1.0f / r_lab[threadIdx.x];
            for (int k = 0; k < NBIN; k++) {
                const float nm = r_num[threadIdx.x * NBIN + k];
                const float dn = r_den[threadIdx.x * NBIN + k];
                pd += nm;
                pn += dn;
                ap += (pd / pn) * (nm * invLab);
            }
        }
        #pragma unroll
        for (int off = 16; off; off >>= 1) ap += __shfl_xor_sync(0xFFFFFFFFu, ap, off);
        if (threadIdx.x == 0) {
            out[0] = ap / (float)B;
            g_ticket = 0;              // reset for the next graph replay
        }
    }
}

// ---------------------------------------------------------------------------
extern "C" void kernel_launch(void* const* d_in, const int* in_sizes, int n_in,
                              void* d_out, int out_size) {
    const float4* qX4    = (const float4*)d_in[0];
    const float4* dXs4   = (const float4*)d_in[1];
    const int*    labels = (const int*)d_in[2];
    float* out = (float*)d_out;

    const int M = 128;
    const int B = in_sizes[0] / M;               // 16
    const int N = in_sizes[1] / in_sizes[0];     // 50000

    // One exact wave at 4 blocks/SM: 148 * 4 = 592 blocks (B*S = 16*37).
    int S = (148 * 4) / B;                       // 37 for B=16
    if (S < 1) S = 1;
    if ((size_t)B * S > MAX_SLOTS) S = MAX_SLOTS / B;

    qap_main<<<B * S, WARPS_PER_BLOCK * 32>>>(qX4, dXs4, labels, out, B, N, S);
}

// round 12
// speedup vs baseline: 1.2710x; 1.0176x over previous
#include <cuda_runtime.h>
#include <cuda_bf16.h>

#define NBIN 25
#define WARPS_PER_BLOCK 8
#define MAX_B 64
#define MAX_SLOTS 1024

// Per-block partial sums, written with plain stores every launch (no zeroing
// needed). Layout: slot = s*B + b so the last-block reduction reads are
// coalesced (stride B*NBIN across thread index).
__device__ float g_pnum[MAX_SLOTS * NBIN];
__device__ float g_pden[MAX_SLOTS * NBIN];
__device__ float g_plab[MAX_SLOTS];
__device__ unsigned int g_ticket = 0;   // reset to 0 by the last block each run

// ---------------------------------------------------------------------------
// Single fused kernel. 8 lanes per row, 4 rows per group.
// Work unit = one 4-row group; each warp owns a CONTIGUOUS balanced range of
// groups (counts differ by <=1 -> 1.8% imbalance vs 13.7% with 32-row tiles),
// and runs a persistent double-buffered load pipeline across its whole range
// (group g+1's 4 LDG.128 + label word issued before group g's shuffle chain).
// 64 regs @ 4 blocks/SM. Plain float4 loads — cache hints regressed DRAM
// 6.3 -> 4.2 TB/s (R4). Reg cap below 64 serializes loads (R6).
// ---------------------------------------------------------------------------
__global__ __launch_bounds__(WARPS_PER_BLOCK * 32, 4)
void qap_main(const float4* __restrict__ qX4,
              const float4* __restrict__ dXs4,
              const int*    __restrict__ labels,
              float* __restrict__ out,
              int B, int N, int S) {
    const int b    = blockIdx.x / S;     // batch
    const int s    = blockIdx.x - b * S; // slice within batch
    const int lane = threadIdx.x & 31;
    const int sub  = lane & 7;           // slice within row (8 lanes/row)
    const int grp  = lane >> 3;          // row within 4-row group
    const int gw     = s * WARPS_PER_BLOCK + (threadIdx.x >> 5);
    const int nWarps = S * WARPS_PER_BLOCK;

    // Per-lane slices of qX[b]: float4 indices sub + 8j.
    float4 qv[4];
    #pragma unroll
    for (int j = 0; j < 4; j++) qv[j] = qX4[(size_t)b * 32 + sub + 8 * j];

    // ||q||, reduced over the 8-lane group.
    float qs = 0.0f;
    #pragma unroll
    for (int j = 0; j < 4; j++)
        qs += qv[j].x * qv[j].x + qv[j].y * qv[j].y + qv[j].z * qv[j].z + qv[j].w * qv[j].w;
    #pragma unroll
    for (int off = 4; off; off >>= 1) qs += __shfl_xor_sync(0xFFFFFFFFu, qs, off);
    const float invqn = 1.0f / fmaxf(sqrtf(qs), 1e-8f);

    const float4* __restrict__ drow = dXs4   + (size_t)b * N * 32;
    const int*    __restrict__ lrow = labels + (size_t)b * N;

    // Lane k accumulates bin k. DELTA = 2/(NBIN-1) = 1/12.
    const float ck   = 1.0f - (float)lane * (2.0f / (float)(NBIN - 1));
    const float invD = (float)(NBIN - 1) * 0.5f;   // 12

    float accNum = 0.0f, accDen = 0.0f, accLab = 0.0f;

    // Contiguous balanced partition of 4-row groups.
    const int groupsTotal = (N + 3) >> 2;
    const int g0 = (int)(((long long)gw       * groupsTotal) / nWarps);
    const int g1 = (int)(((long long)(gw + 1) * groupsTotal) / nWarps);

    float4 x[4], xn[4];
    float labf = 0.0f, labn;

    if (g0 < g1) {
        const int r0  = g0 << 2;
        const int row = min(r0 + grp, N - 1);          // clamp (unused rows masked later)
        const float4* __restrict__ p = drow + (size_t)row * 32 + sub;
        #pragma unroll
        for (int j = 0; j < 4; j++) x[j] = p[8 * j];
        const int li = r0 + (lane & 3);
        labf = (li < N) ? (float)lrow[li] : 0.0f;      // 4 words, broadcast sector
    }

    for (int g = g0; g < g1; g++) {
        const int r0 = g << 2;
        // ---- prefetch next group while this group's loads drain ----
        if (g + 1 < g1) {
            const int nr0 = (g + 1) << 2;
            const int row = min(nr0 + grp, N - 1);
            const float4* __restrict__ p = drow + (size_t)row * 32 + sub;
            #pragma unroll
            for (int j = 0; j < 4; j++) xn[j] = p[8 * j];
            const int li = nr0 + (lane & 3);
            labn = (li < N) ? (float)lrow[li] : 0.0f;
        }

        float d = 0.0f, sq = 0.0f;
        #pragma unroll
        for (int j = 0; j < 4; j++) {
            d  += qv[j].x * x[j].x + qv[j].y * x[j].y + qv[j].z * x[j].z + qv[j].w * x[j].w;
            sq += x[j].x * x[j].x + x[j].y * x[j].y + x[j].z * x[j].z + x[j].w * x[j].w;
        }
        #pragma unroll
        for (int off = 4; off; off >>= 1) {
            d  += __shfl_xor_sync(0xFFFFFFFFu, d,  off);
            sq += __shfl_xor_sync(0xFFFFFFFFu, sq, off);
        }
        // sim = d / (qn * max(sqrt(sq),1e-8)); sq clamp -> rsqrt form.
        const float sim = d * invqn * rsqrtf(fmaxf(sq, 1e-16f));

        if (lane < 4) accLab += labf;      // lanes 0-3 hold rows r0+0..3 exactly once

        #pragma unroll
        for (int r = 0; r < 4; r++) {
            if (r0 + r >= N) break;        // uniform; never taken when N%4==0
            const float simr = __shfl_sync(0xFFFFFFFFu, sim,  r << 3);
            const float labr = __shfl_sync(0xFFFFFFFFu, labf, r);
            const float sa = fmaxf(0.0f, fmaf(-invD, fabsf(simr - ck), 1.0f));
            accDen += sa;
            accNum += sa * labr;
        }

        #pragma unroll
        for (int j = 0; j < 4; j++) x[j] = xn[j];      // renamed, not moved
        labf = labn;
    }

    // Warp-reduce the per-lane label partials.
    #pragma unroll
    for (int off = 16; off; off >>= 1)
        accLab += __shfl_xor_sync(0xFFFFFFFFu, accLab, off);

    // Block-level combine in smem, then one plain store per bin.
    __shared__ float s_num[NBIN], s_den[NBIN], s_lab;
    if (threadIdx.x < NBIN) { s_num[threadIdx.x] = 0.0f; s_den[threadIdx.x] = 0.0f; }
    if (threadIdx.x == 0) s_lab = 0.0f;
    __syncthreads();
    if (lane < NBIN) {
        atomicAdd(&s_den[lane], accDen);
        atomicAdd(&s_num[lane], accNum);
    }
    if (lane == 0) atomicAdd(&s_lab, accLab);
    __syncthreads();

    const int slot = s * B + b;
    if (threadIdx.x < NBIN) {
        g_pnum[slot * NBIN + threadIdx.x] = s_num[threadIdx.x];
        g_pden[slot * NBIN + threadIdx.x] = s_den[threadIdx.x];
    }
    if (threadIdx.x == 0) g_plab[slot] = s_lab;

    // ---- last-block reduction (threadfence-reduction pattern) ----
    __shared__ unsigned int s_last;
    __threadfence();
    if (threadIdx.x == 0) {
        unsigned int old = atomicAdd(&g_ticket, 1u);
        s_last = (old == (unsigned int)(gridDim.x - 1)) ? 1u : 0u;
    }
    __syncthreads();
    if (!s_last) return;

    // Partials are L2-hot here. Keep pragma-free (register hygiene).
    __shared__ float r_num[MAX_B * NBIN], r_den[MAX_B * NBIN], r_lab[MAX_B];
    const int total = B * NBIN;
    for (int i = threadIdx.x; i < total; i += blockDim.x) {
        float a = 0.0f, c = 0.0f;
        for (int sidx = 0; sidx < S; sidx++) {     // coalesced: stride = total
            a += g_pnum[sidx * total + i];
            c += g_pden[sidx * total + i];
        }
        r_num[i] = a; r_den[i] = c;
    }
    if (threadIdx.x < B) {
        float l = 0.0f;
        for (int sidx = 0; sidx < S; sidx++) l += g_plab[sidx * B + threadIdx.x];
        r_lab[threadIdx.x] = l;
    }
    __syncthreads();

    if (threadIdx.x < 32) {
        float ap = 0.0f;
        if (threadIdx.x < B) {
            float pd = 0.0f;           // cumsum num_per_bin  ("pDen")
            float pn = 1e-16f;         // EPS_P + cumsum den_per_bin ("pNum")
            const float invLab = 1.0f / r_lab[threadIdx.x];
            for (int k = 0; k < NBIN; k++) {
                const float nm = r_num[threadIdx.x * NBIN + k];
                const float dn = r_den[threadIdx.x * NBIN + k];
                pd += nm;
                pn += dn;
                ap += (pd / pn) * (nm * invLab);
            }
        }
        #pragma unroll
        for (int off = 16; off; off >>= 1) ap += __shfl_xor_sync(0xFFFFFFFFu, ap, off);
        if (threadIdx.x == 0) {
            out[0] = ap / (float)B;
            g_ticket = 0;              // reset for the next graph replay
        }
    }
}

// ---------------------------------------------------------------------------
extern "C" void kernel_launch(void* const* d_in, const int* in_sizes, int n_in,
                              void* d_out, int out_size) {
    const float4* qX4    = (const float4*)d_in[0];
    const float4* dXs4   = (const float4*)d_in[1];
    const int*    labels = (const int*)d_in[2];
    float* out = (float*)d_out;

    const int M = 128;
    const int B = in_sizes[0] / M;               // 16
    const int N = in_sizes[1] / in_sizes[0];     // 50000

    // One exact wave at 4 blocks/SM: 148 * 4 = 592 blocks (B*S = 16*37).
    int S = (148 * 4) / B;                       // 37 for B=16
    if (S < 1) S = 1;
    if ((size_t)B * S > MAX_SLOTS) S = MAX_SLOTS / B;

    qap_main<<<B * S, WARPS_PER_BLOCK * 32>>>(qX4, dXs4, labels, out, B, N, S);
}